// round 6
// baseline (speedup 1.0000x reference)
#include <cuda_runtime.h>
#include <cmath>
#include <cstdint>

#define BB 4
#define NN 4096
#define CC 256
#define KK 512
#define KNNK 32

// ---------------- scratch (no allocations allowed) ----------------
__device__ float    g_dist[(size_t)BB * NN * NN];   // 268 MB pairwise distances
__device__ float    g_x2[BB * NN];
__device__ float    g_density[BB * NN];
__device__ float    g_score[BB * NN];
__device__ unsigned g_maxbits[BB];
__device__ int      g_index_down[BB * KK];

// ---------------- threefry2x32 (bit-exact JAX PRNG, key = (0,1)) ----------------
__device__ __forceinline__ unsigned rotl32(unsigned x, int r) {
    return (x << r) | (x >> (32 - r));
}

__device__ void threefry2x32(unsigned k1, unsigned k2, unsigned x0, unsigned x1,
                             unsigned& o0, unsigned& o1) {
    unsigned ks0 = k1, ks1 = k2, ks2 = k1 ^ k2 ^ 0x1BD11BDAu;
    const int ra[4] = {13, 15, 26, 6};
    const int rb[4] = {17, 29, 16, 24};
    x0 += ks0; x1 += ks1;
#pragma unroll
    for (int i = 0; i < 4; i++) { x0 += x1; x1 = rotl32(x1, ra[i]); x1 ^= x0; }
    x0 += ks1; x1 += ks2 + 1u;
#pragma unroll
    for (int i = 0; i < 4; i++) { x0 += x1; x1 = rotl32(x1, rb[i]); x1 ^= x0; }
    x0 += ks2; x1 += ks0 + 2u;
#pragma unroll
    for (int i = 0; i < 4; i++) { x0 += x1; x1 = rotl32(x1, ra[i]); x1 ^= x0; }
    x0 += ks0; x1 += ks1 + 3u;
#pragma unroll
    for (int i = 0; i < 4; i++) { x0 += x1; x1 = rotl32(x1, rb[i]); x1 ^= x0; }
    x0 += ks1; x1 += ks2 + 4u;
#pragma unroll
    for (int i = 0; i < 4; i++) { x0 += x1; x1 = rotl32(x1, ra[i]); x1 ^= x0; }
    x0 += ks2; x1 += ks0 + 5u;
    o0 = x0; o1 = x1;
}

// JAX threefry_partitionable (default since 0.4.30) random_bits for 32-bit:
// counter = uint64 iota -> threefry2x32(key, hi32(i)=0, lo32(i)=i), bits = o0 ^ o1.
// uniform[0,1): bitcast((bits >> 9) | 0x3f800000) - 1.
__device__ float jax_uniform_noise(unsigned gid) {
    unsigned o0, o1;
    threefry2x32(0u, 1u, 0u, gid, o0, o1);
    unsigned bits = o0 ^ o1;
    unsigned fb = (bits >> 9) | 0x3f800000u;
    return __uint_as_float(fb) - 1.0f;
}

// ---------------- glibc expf (bit-exact port of sysdeps/ieee754/flt-32/e_expf.c) ----
// N = 32 table: tab[j] = bits(2^(j/32) correctly rounded) - (j << 47)
__device__ __constant__ unsigned long long c_exp_tab[32] = {
    0x3ff0000000000000ULL, 0x3fefd9b0d3158574ULL, 0x3fefb5586cf9890fULL, 0x3fef9301d0125b51ULL,
    0x3fef72b83c7d517bULL, 0x3fef54873168b9aaULL, 0x3fef387a6e756238ULL, 0x3fef1e9df51fdee1ULL,
    0x3fef06fe0a31b715ULL, 0x3feef1a7373aa9cbULL, 0x3feedea64c123422ULL, 0x3feece086061892dULL,
    0x3feebfdad5362a27ULL, 0x3feeb42b569d4f82ULL, 0x3feeab07dd485429ULL, 0x3feea47eb03a5585ULL,
    0x3feea09e667f3bcdULL, 0x3fee9f75e8ec5f74ULL, 0x3feea11473eb0187ULL, 0x3feea589994cce13ULL,
    0x3feeace5422aa0dbULL, 0x3feeb737b0cdc5e5ULL, 0x3feec49182a3f090ULL, 0x3feed503b23e255dULL,
    0x3feee89f995ad3adULL, 0x3feeff76f2fb5e47ULL, 0x3fef199bdd85529cULL, 0x3fef3720dcef9069ULL,
    0x3fef5818dcfba487ULL, 0x3fef7c97337b9b5fULL, 0x3fefa4afa2a490daULL, 0x3fefd0765b6e4540ULL
};

__device__ float glibc_expf(float x) {
    const double InvLn2N = 0x1.71547652b82fep+5;          // N/ln2, N=32
    const double C0 = 0x1.c6af84b912394p-5 / (32.0 * 32.0 * 32.0);
    const double C1 = 0x1.ebfce50fac4f3p-3 / (32.0 * 32.0);
    const double C2 = 0x1.62e42ff0c52d6p-1 / 32.0;
    double xd = (double)x;
    double z  = InvLn2N * xd;
    double kd = rint(z);                                  // nearest-even
    long long kis = __double2ll_rn(z);                    // nearest-even
    unsigned long long ki = (unsigned long long)kis;
    double r = z - kd;
    unsigned long long t = c_exp_tab[ki & 31] + (ki << 47);
    double s = __longlong_as_double((long long)t);
    double zz = fma(C0, r, C1);
    double r2 = r * r;
    double y  = fma(C2, r, 1.0);
    y = fma(zz, r2, y);
    return (float)(y * s);
}

// ---------------- kernels ----------------

// x2 = sum(x*x, -1): 4 lane accumulators over k mod 4, unfused mul+add,
// horizontal combine (a0+a2)+(a1+a3).
__global__ void x2_kernel(const float* __restrict__ x) {
    int row = blockIdx.x * blockDim.x + threadIdx.x;
    if (row >= BB * NN) return;
    const float4* xp = (const float4*)(x + (size_t)row * CC);
    float a0 = 0.f, a1 = 0.f, a2 = 0.f, a3 = 0.f;
#pragma unroll 8
    for (int kb = 0; kb < CC / 4; kb++) {
        float4 v = xp[kb];
        a0 = __fadd_rn(a0, __fmul_rn(v.x, v.x));
        a1 = __fadd_rn(a1, __fmul_rn(v.y, v.y));
        a2 = __fadd_rn(a2, __fmul_rn(v.z, v.z));
        a3 = __fadd_rn(a3, __fmul_rn(v.w, v.w));
    }
    g_x2[row] = __fadd_rn(__fadd_rn(a0, a2), __fadd_rn(a1, a3));
}

// 128x128 tile fp32 GEMM -> distances.  dist = sqrt(max(x2i + x2j - 2*dot, 0)) / 16
// Single fused-FMA chain ascending k per output.
__global__ __launch_bounds__(256, 2) void dist_kernel(const float* __restrict__ x) {
    const int TS = 128, KC = 8;
    int b  = blockIdx.z;
    int it = blockIdx.y * TS;
    int jt = blockIdx.x * TS;
    const float* xb = x + (size_t)b * NN * CC;

    __shared__ float As[KC][TS];
    __shared__ float Bs[KC][TS];

    int tid = threadIdx.x;         // 256 threads
    int tx = tid & 15, ty = tid >> 4;

    float acc[8][8];
#pragma unroll
    for (int u = 0; u < 8; u++)
#pragma unroll
        for (int v = 0; v < 8; v++) acc[u][v] = 0.f;

    for (int k0 = 0; k0 < CC; k0 += KC) {
        int e   = tid * 4;
        int row = e >> 3;      // /KC
        int kk  = e & 7;       // %KC  (0 or 4)
        float4 av = *(const float4*)(&xb[(size_t)(it + row) * CC + k0 + kk]);
        float4 bv = *(const float4*)(&xb[(size_t)(jt + row) * CC + k0 + kk]);
        As[kk + 0][row] = av.x; As[kk + 1][row] = av.y;
        As[kk + 2][row] = av.z; As[kk + 3][row] = av.w;
        Bs[kk + 0][row] = bv.x; Bs[kk + 1][row] = bv.y;
        Bs[kk + 2][row] = bv.z; Bs[kk + 3][row] = bv.w;
        __syncthreads();

#pragma unroll
        for (int kc = 0; kc < KC; kc++) {
            float4 a0 = *(const float4*)(&As[kc][ty * 8]);
            float4 a1 = *(const float4*)(&As[kc][ty * 8 + 4]);
            float4 b0 = *(const float4*)(&Bs[kc][tx * 8]);
            float4 b1 = *(const float4*)(&Bs[kc][tx * 8 + 4]);
            float a[8] = {a0.x, a0.y, a0.z, a0.w, a1.x, a1.y, a1.z, a1.w};
            float bb2[8] = {b0.x, b0.y, b0.z, b0.w, b1.x, b1.y, b1.z, b1.w};
#pragma unroll
            for (int u = 0; u < 8; u++)
#pragma unroll
                for (int v = 0; v < 8; v++)
                    acc[u][v] += a[u] * bb2[v];   // FFMA chain, k ascending
        }
        __syncthreads();
    }

#pragma unroll
    for (int u = 0; u < 8; u++) {
        int i = it + ty * 8 + u;
        float x2i = g_x2[b * NN + i];
        float* drow = g_dist + ((size_t)b * NN + i) * NN;
#pragma unroll
        for (int v = 0; v < 8; v++) {
            int j = jt + tx * 8 + v;
            float s  = __fadd_rn(x2i, g_x2[b * NN + j]);
            float d2 = __fadd_rn(s, -__fmul_rn(2.0f, acc[u][v]));
            d2 = fmaxf(d2, 0.0f);
            drow[j] = __fmul_rn(__fsqrt_rn(d2), 0.0625f);
        }
    }
}

// per-row: 32 smallest distances (exact multiset, ascending) -> density
__global__ void knn_density_kernel() {
    int row = blockIdx.x;                 // b*NN + i
    const float* dr = g_dist + (size_t)row * NN;
    __shared__ float vals[NN];            // 16 KB
    __shared__ float rv[256];
    __shared__ int   ri[256];
    __shared__ float sel[KNNK];
    int tid = threadIdx.x;

    for (int j = tid; j < NN; j += 256) vals[j] = dr[j];
    __syncthreads();

    for (int it = 0; it < KNNK; it++) {
        float mv = 3.4e38f; int mi = -1;
        for (int j = tid; j < NN; j += 256) {
            float v = vals[j];
            if (v < mv) { mv = v; mi = j; }
        }
        rv[tid] = mv; ri[tid] = mi;
        __syncthreads();
        for (int s = 128; s > 0; s >>= 1) {
            if (tid < s && rv[tid + s] < rv[tid]) {
                rv[tid] = rv[tid + s]; ri[tid] = ri[tid + s];
            }
            __syncthreads();
        }
        if (tid == 0) {
            sel[it] = rv[0];
            vals[ri[0]] = 3.4e38f;
        }
        __syncthreads();
    }

    if (tid == 0) {
        // lanes mod 4, sequential within lane, unfused mul+add
        float a[4] = {0.f, 0.f, 0.f, 0.f};
#pragma unroll
        for (int i = 0; i < KNNK; i += 4) {
#pragma unroll
            for (int l = 0; l < 4; l++)
                a[l] = __fadd_rn(a[l], __fmul_rn(sel[i + l], sel[i + l]));
        }
        float sum  = __fadd_rn(__fadd_rn(a[0], a[2]), __fadd_rn(a[1], a[3]));
        float mean = __fmul_rn(sum, 0.03125f);     // /32 exact
        float dens = glibc_expf(-mean);
        float noise = jax_uniform_noise((unsigned)row);
        g_density[row] = __fadd_rn(dens, __fmul_rn(noise, 1e-6f));
    }
}

__global__ void max_init_kernel() {
    if (threadIdx.x < BB) g_maxbits[threadIdx.x] = 0u;
}

__global__ void max_kernel() {
    int b = blockIdx.y;
    const float* db = g_dist + (size_t)b * NN * NN;
    float m = 0.f;
    for (size_t i = (size_t)blockIdx.x * blockDim.x + threadIdx.x;
         i < (size_t)NN * NN; i += (size_t)gridDim.x * blockDim.x)
        m = fmaxf(m, db[i]);
    __shared__ float sm[256];
    sm[threadIdx.x] = m;
    __syncthreads();
    for (int s = 128; s > 0; s >>= 1) {
        if (threadIdx.x < s) sm[threadIdx.x] = fmaxf(sm[threadIdx.x], sm[threadIdx.x + s]);
        __syncthreads();
    }
    if (threadIdx.x == 0) atomicMax(&g_maxbits[b], __float_as_uint(sm[0]));
}

// dist-to-nearest-higher-density (exact min, order-free), score = dist * density
__global__ void distmin_kernel() {
    int row = blockIdx.x;
    int b = row >> 12;
    const float* dr   = g_dist + (size_t)row * NN;
    const float* dens = g_density + b * NN;
    float di   = g_density[row];
    float dmax = __uint_as_float(g_maxbits[b]);
    float mv = dmax;
    for (int j = threadIdx.x; j < NN; j += 256) {
        if (dens[j] > di) mv = fminf(mv, dr[j]);
    }
    __shared__ float sm[256];
    sm[threadIdx.x] = mv;
    __syncthreads();
    for (int s = 128; s > 0; s >>= 1) {
        if (threadIdx.x < s) sm[threadIdx.x] = fminf(sm[threadIdx.x], sm[threadIdx.x + s]);
        __syncthreads();
    }
    if (threadIdx.x == 0) g_score[row] = __fmul_rn(sm[0], di);
}

// bitonic sort, key = (~score_bits << 32) | idx  -> top-K with lax.top_k ties
__global__ void topk_kernel(float* __restrict__ out_indexdown) {
    __shared__ unsigned long long keys[NN];   // 32 KB
    int b = blockIdx.x;
    int tid = threadIdx.x;                    // 512 threads
    for (int j = tid; j < NN; j += 512) {
        unsigned sb = __float_as_uint(g_score[b * NN + j]);
        keys[j] = ((unsigned long long)(~sb) << 32) | (unsigned)j;
    }
    __syncthreads();
    for (unsigned k = 2; k <= NN; k <<= 1) {
        for (unsigned st = k >> 1; st > 0; st >>= 1) {
            for (unsigned i = tid; i < NN; i += 512) {
                unsigned ixj = i ^ st;
                if (ixj > i) {
                    unsigned long long a = keys[i], c = keys[ixj];
                    bool up = ((i & k) == 0);
                    bool swap = up ? (a > c) : (a < c);
                    if (swap) { keys[i] = c; keys[ixj] = a; }
                }
            }
            __syncthreads();
        }
    }
    int idx = (int)(keys[tid] & 0xFFFFFFFFull);
    g_index_down[b * KK + tid] = idx;
    out_indexdown[b * KK + tid] = (float)idx;
}

// idx_cluster[b,j] = argmin_kk dist[b, center_kk, j]  (first-min, strict <)
__global__ void assign_kernel(float* __restrict__ out_idxcluster) {
    int b = blockIdx.y;
    int j = blockIdx.x * 256 + threadIdx.x;
    __shared__ int cen[KK];
    for (int t = threadIdx.x; t < KK; t += 256) cen[t] = g_index_down[b * KK + t];
    __syncthreads();
    const float* db = g_dist + (size_t)b * NN * NN;
    float best = 3.4e38f; int bi = 0;
    for (int kk = 0; kk < KK; kk++) {
        float v = db[(size_t)cen[kk] * NN + j];
        if (v < best) { best = v; bi = kk; }
    }
    out_idxcluster[b * NN + j] = (float)bi;
}

__global__ void scatter_kernel(float* __restrict__ out_idxcluster) {
    int t = blockIdx.x * 256 + threadIdx.x;
    if (t >= BB * KK) return;
    int b = t >> 9, kk = t & (KK - 1);
    out_idxcluster[b * NN + g_index_down[t]] = (float)kk;
}

__global__ void xdown_kernel(const float* __restrict__ x, float* __restrict__ out_xdown) {
    int t = blockIdx.x * 256 + threadIdx.x;
    if (t >= BB * KK * CC) return;
    int c = t & (CC - 1);
    int rest = t >> 8;
    int kk = rest & (KK - 1);
    int b = rest >> 9;
    out_xdown[t] = x[((size_t)b * NN + g_index_down[b * KK + kk]) * CC + c];
}

// ---------------- launch ----------------
extern "C" void kernel_launch(void* const* d_in, const int* in_sizes, int n_in,
                              void* d_out, int out_size) {
    const float* x = (const float*)d_in[0];
    float* out = (float*)d_out;
    float* out_indexdown  = out;                       // B*K
    float* out_idxcluster = out + BB * KK;             // B*N
    float* out_xdown      = out + BB * KK + BB * NN;   // B*K*C

    x2_kernel<<<(BB * NN + 255) / 256, 256>>>(x);

    dim3 gg(NN / 128, NN / 128, BB);
    dist_kernel<<<gg, 256>>>(x);

    knn_density_kernel<<<BB * NN, 256>>>();

    max_init_kernel<<<1, 32>>>();
    max_kernel<<<dim3(512, BB), 256>>>();

    distmin_kernel<<<BB * NN, 256>>>();

    topk_kernel<<<BB, 512>>>(out_indexdown);

    assign_kernel<<<dim3(NN / 256, BB), 256>>>(out_idxcluster);
    scatter_kernel<<<(BB * KK + 255) / 256, 256>>>(out_idxcluster);
    xdown_kernel<<<(BB * KK * CC + 255) / 256, 256>>>(x, out_xdown);
}

// round 7
// speedup vs baseline: 1.3344x; 1.3344x over previous
#include <cuda_runtime.h>
#include <cmath>
#include <cstdint>

#define BB 4
#define NN 4096
#define CC 256
#define KK 512
#define KNNK 32

// ---------------- scratch (no allocations allowed) ----------------
__device__ float    g_dist[(size_t)BB * NN * NN];   // 268 MB pairwise distances
__device__ float    g_x2[BB * NN];
__device__ float    g_density[BB * NN];
__device__ float    g_score[BB * NN];
__device__ unsigned g_maxbits[BB];
__device__ int      g_index_down[BB * KK];

// ---------------- threefry2x32 (bit-exact JAX PRNG, key = (0,1)) ----------------
__device__ __forceinline__ unsigned rotl32(unsigned x, int r) {
    return (x << r) | (x >> (32 - r));
}

__device__ void threefry2x32(unsigned k1, unsigned k2, unsigned x0, unsigned x1,
                             unsigned& o0, unsigned& o1) {
    unsigned ks0 = k1, ks1 = k2, ks2 = k1 ^ k2 ^ 0x1BD11BDAu;
    const int ra[4] = {13, 15, 26, 6};
    const int rb[4] = {17, 29, 16, 24};
    x0 += ks0; x1 += ks1;
#pragma unroll
    for (int i = 0; i < 4; i++) { x0 += x1; x1 = rotl32(x1, ra[i]); x1 ^= x0; }
    x0 += ks1; x1 += ks2 + 1u;
#pragma unroll
    for (int i = 0; i < 4; i++) { x0 += x1; x1 = rotl32(x1, rb[i]); x1 ^= x0; }
    x0 += ks2; x1 += ks0 + 2u;
#pragma unroll
    for (int i = 0; i < 4; i++) { x0 += x1; x1 = rotl32(x1, ra[i]); x1 ^= x0; }
    x0 += ks0; x1 += ks1 + 3u;
#pragma unroll
    for (int i = 0; i < 4; i++) { x0 += x1; x1 = rotl32(x1, rb[i]); x1 ^= x0; }
    x0 += ks1; x1 += ks2 + 4u;
#pragma unroll
    for (int i = 0; i < 4; i++) { x0 += x1; x1 = rotl32(x1, ra[i]); x1 ^= x0; }
    x0 += ks2; x1 += ks0 + 5u;
    o0 = x0; o1 = x1;
}

// JAX threefry_partitionable random_bits (32-bit): counter = uint64 iota ->
// threefry2x32(key, 0, i), bits = o0 ^ o1. uniform = bitcast((bits>>9)|1.0f)-1.
__device__ float jax_uniform_noise(unsigned gid) {
    unsigned o0, o1;
    threefry2x32(0u, 1u, 0u, gid, o0, o1);
    unsigned bits = o0 ^ o1;
    unsigned fb = (bits >> 9) | 0x3f800000u;
    return __uint_as_float(fb) - 1.0f;
}

// ---------------- glibc expf (bit-exact port of sysdeps/ieee754/flt-32/e_expf.c) ----
__device__ __constant__ unsigned long long c_exp_tab[32] = {
    0x3ff0000000000000ULL, 0x3fefd9b0d3158574ULL, 0x3fefb5586cf9890fULL, 0x3fef9301d0125b51ULL,
    0x3fef72b83c7d517bULL, 0x3fef54873168b9aaULL, 0x3fef387a6e756238ULL, 0x3fef1e9df51fdee1ULL,
    0x3fef06fe0a31b715ULL, 0x3feef1a7373aa9cbULL, 0x3feedea64c123422ULL, 0x3feece086061892dULL,
    0x3feebfdad5362a27ULL, 0x3feeb42b569d4f82ULL, 0x3feeab07dd485429ULL, 0x3feea47eb03a5585ULL,
    0x3feea09e667f3bcdULL, 0x3fee9f75e8ec5f74ULL, 0x3feea11473eb0187ULL, 0x3feea589994cce13ULL,
    0x3feeace5422aa0dbULL, 0x3feeb737b0cdc5e5ULL, 0x3feec49182a3f090ULL, 0x3feed503b23e255dULL,
    0x3feee89f995ad3adULL, 0x3feeff76f2fb5e47ULL, 0x3fef199bdd85529cULL, 0x3fef3720dcef9069ULL,
    0x3fef5818dcfba487ULL, 0x3fef7c97337b9b5fULL, 0x3fefa4afa2a490daULL, 0x3fefd0765b6e4540ULL
};

__device__ float glibc_expf(float x) {
    const double InvLn2N = 0x1.71547652b82fep+5;          // N/ln2, N=32
    const double C0 = 0x1.c6af84b912394p-5 / (32.0 * 32.0 * 32.0);
    const double C1 = 0x1.ebfce50fac4f3p-3 / (32.0 * 32.0);
    const double C2 = 0x1.62e42ff0c52d6p-1 / 32.0;
    double xd = (double)x;
    double z  = InvLn2N * xd;
    double kd = rint(z);
    long long kis = __double2ll_rn(z);
    unsigned long long ki = (unsigned long long)kis;
    double r = z - kd;
    unsigned long long t = c_exp_tab[ki & 31] + (ki << 47);
    double s = __longlong_as_double((long long)t);
    double zz = fma(C0, r, C1);
    double r2 = r * r;
    double y  = fma(C2, r, 1.0);
    y = fma(zz, r2, y);
    return (float)(y * s);
}

// ---------------- kernels ----------------

// x2 = sum(x*x, -1): 4 lane accumulators over k mod 4, unfused mul+add,
// horizontal combine (a0+a2)+(a1+a3). Also resets g_maxbits for this call.
__global__ void x2_kernel(const float* __restrict__ x) {
    int row = blockIdx.x * blockDim.x + threadIdx.x;
    if (blockIdx.x == 0 && threadIdx.x < BB) g_maxbits[threadIdx.x] = 0u;
    if (row >= BB * NN) return;
    const float4* xp = (const float4*)(x + (size_t)row * CC);
    float a0 = 0.f, a1 = 0.f, a2 = 0.f, a3 = 0.f;
#pragma unroll 8
    for (int kb = 0; kb < CC / 4; kb++) {
        float4 v = xp[kb];
        a0 = __fadd_rn(a0, __fmul_rn(v.x, v.x));
        a1 = __fadd_rn(a1, __fmul_rn(v.y, v.y));
        a2 = __fadd_rn(a2, __fmul_rn(v.z, v.z));
        a3 = __fadd_rn(a3, __fmul_rn(v.w, v.w));
    }
    g_x2[row] = __fadd_rn(__fadd_rn(a0, a2), __fadd_rn(a1, a3));
}

// Triangular fp32 GEMM -> distances, with symmetric mirror writes.
// dist[i][j] = sqrt(max(x2i + x2j - 2*dot, 0))/16 is bit-symmetric (commuted
// FFMA operands and commuted fadd round identically), so only jt>=it tiles are
// computed; each off-diagonal tile is written twice (direct + transposed).
// Also accumulates the per-batch global max via atomicMax (positive floats:
// uint compare == float compare).
#define NTILE 32            // NN/128
#define NPAIRS 528          // NTILE*(NTILE+1)/2
__device__ __forceinline__ int tri_base(int i) { return i * (2 * NTILE + 1 - i) / 2; }

__global__ __launch_bounds__(256, 2) void dist_kernel(const float* __restrict__ x) {
    const int TS = 128, KC = 8;
    int b = blockIdx.z;
    int l = blockIdx.x;
    // decode l -> (ti, tj), tj >= ti
    int ti = (int)((2 * NTILE + 1 - sqrtf((float)((2 * NTILE + 1) * (2 * NTILE + 1) - 8 * l))) * 0.5f);
    if (ti > 0 && tri_base(ti) > l) ti--;
    while (tri_base(ti + 1) <= l) ti++;
    int tj = ti + (l - tri_base(ti));
    int it = ti * TS;
    int jt = tj * TS;
    const float* xb = x + (size_t)b * NN * CC;

    __shared__ float As[KC][TS];
    __shared__ float Bs[KC][TS];

    int tid = threadIdx.x;         // 256 threads
    int tx = tid & 15, ty = tid >> 4;

    float acc[8][8];
#pragma unroll
    for (int u = 0; u < 8; u++)
#pragma unroll
        for (int v = 0; v < 8; v++) acc[u][v] = 0.f;

    for (int k0 = 0; k0 < CC; k0 += KC) {
        int e   = tid * 4;
        int row = e >> 3;      // /KC
        int kk  = e & 7;       // %KC  (0 or 4)
        float4 av = *(const float4*)(&xb[(size_t)(it + row) * CC + k0 + kk]);
        float4 bv = *(const float4*)(&xb[(size_t)(jt + row) * CC + k0 + kk]);
        As[kk + 0][row] = av.x; As[kk + 1][row] = av.y;
        As[kk + 2][row] = av.z; As[kk + 3][row] = av.w;
        Bs[kk + 0][row] = bv.x; Bs[kk + 1][row] = bv.y;
        Bs[kk + 2][row] = bv.z; Bs[kk + 3][row] = bv.w;
        __syncthreads();

#pragma unroll
        for (int kc = 0; kc < KC; kc++) {
            float4 a0 = *(const float4*)(&As[kc][ty * 8]);
            float4 a1 = *(const float4*)(&As[kc][ty * 8 + 4]);
            float4 b0 = *(const float4*)(&Bs[kc][tx * 8]);
            float4 b1 = *(const float4*)(&Bs[kc][tx * 8 + 4]);
            float a[8] = {a0.x, a0.y, a0.z, a0.w, a1.x, a1.y, a1.z, a1.w};
            float bb2[8] = {b0.x, b0.y, b0.z, b0.w, b1.x, b1.y, b1.z, b1.w};
#pragma unroll
            for (int u = 0; u < 8; u++)
#pragma unroll
                for (int v = 0; v < 8; v++)
                    acc[u][v] += a[u] * bb2[v];   // FFMA chain, k ascending
        }
        __syncthreads();
    }

    // convert acc -> distances in place
    float x2i[8], x2j[8];
#pragma unroll
    for (int u = 0; u < 8; u++) x2i[u] = g_x2[b * NN + it + ty * 8 + u];
#pragma unroll
    for (int v = 0; v < 8; v++) x2j[v] = g_x2[b * NN + jt + tx * 8 + v];
    unsigned mbits = 0u;
#pragma unroll
    for (int u = 0; u < 8; u++) {
#pragma unroll
        for (int v = 0; v < 8; v++) {
            float s  = __fadd_rn(x2i[u], x2j[v]);
            float d2 = __fadd_rn(s, -__fmul_rn(2.0f, acc[u][v]));
            d2 = fmaxf(d2, 0.0f);
            float d = __fmul_rn(__fsqrt_rn(d2), 0.0625f);
            acc[u][v] = d;
            mbits = max(mbits, __float_as_uint(d));
        }
    }
    mbits = __reduce_max_sync(0xffffffffu, mbits);
    if ((tid & 31) == 0) atomicMax(&g_maxbits[b], mbits);

    // direct write: row i = it+ty*8+u, cols jt+tx*8 .. +7 (two float4)
#pragma unroll
    for (int u = 0; u < 8; u++) {
        float* drow = g_dist + ((size_t)b * NN + it + ty * 8 + u) * NN + jt + tx * 8;
        float4 w0 = make_float4(acc[u][0], acc[u][1], acc[u][2], acc[u][3]);
        float4 w1 = make_float4(acc[u][4], acc[u][5], acc[u][6], acc[u][7]);
        *(float4*)(drow)     = w0;
        *(float4*)(drow + 4) = w1;
    }
    // mirror write (off-diagonal tiles): row j = jt+tx*8+v, cols it+ty*8 .. +7
    if (it != jt) {
#pragma unroll
        for (int v = 0; v < 8; v++) {
            float* drow = g_dist + ((size_t)b * NN + jt + tx * 8 + v) * NN + it + ty * 8;
            float4 t0 = make_float4(acc[0][v], acc[1][v], acc[2][v], acc[3][v]);
            float4 t1 = make_float4(acc[4][v], acc[5][v], acc[6][v], acc[7][v]);
            *(float4*)(drow)     = t0;
            *(float4*)(drow + 4) = t1;
        }
    }
}

// per-row: 32 smallest distances (exact multiset, ascending) -> density.
// Selection: per-thread min over 16 strided smem slots + redux.sync warp min
// + 8-way combine; removal by bit-match with smem CAS claim. 3 barriers/iter.
__global__ void knn_density_kernel() {
    int row = blockIdx.x;                 // b*NN + i
    const float* dr = g_dist + (size_t)row * NN;
    __shared__ unsigned vals[NN];         // 16 KB (float bits; distances >= 0)
    __shared__ unsigned warpmin[8];
    __shared__ unsigned s_min;
    __shared__ int      s_claim;
    __shared__ float    sel[KNNK];
    int tid  = threadIdx.x;               // 256
    int lane = tid & 31, wid = tid >> 5;
    const unsigned REMOVED = 0xFFFFFFFFu; // NaN bits, > any finite distance

    for (int j = tid; j < NN; j += 256) vals[j] = __float_as_uint(dr[j]);
    __syncthreads();

    for (int it = 0; it < KNNK; it++) {
        unsigned m = REMOVED;
#pragma unroll
        for (int i = 0; i < NN / 256; i++) m = min(m, vals[tid + 256 * i]);
        m = __reduce_min_sync(0xffffffffu, m);
        if (lane == 0) warpmin[wid] = m;
        __syncthreads();
        if (tid == 0) {
            unsigned mm = warpmin[0];
#pragma unroll
            for (int w = 1; w < 8; w++) mm = min(mm, warpmin[w]);
            s_min = mm;
            s_claim = -1;
            sel[it] = __uint_as_float(mm);
        }
        __syncthreads();
        unsigned target = s_min;
#pragma unroll
        for (int i = 0; i < NN / 256; i++) {
            int j = tid + 256 * i;
            if (vals[j] == target) {
                if (atomicCAS(&s_claim, -1, j) == -1) vals[j] = REMOVED;
                break;
            }
        }
        __syncthreads();
    }

    if (tid == 0) {
        // lanes mod 4, sequential within lane, unfused mul+add
        float a[4] = {0.f, 0.f, 0.f, 0.f};
#pragma unroll
        for (int i = 0; i < KNNK; i += 4) {
#pragma unroll
            for (int l = 0; l < 4; l++)
                a[l] = __fadd_rn(a[l], __fmul_rn(sel[i + l], sel[i + l]));
        }
        float sum  = __fadd_rn(__fadd_rn(a[0], a[2]), __fadd_rn(a[1], a[3]));
        float mean = __fmul_rn(sum, 0.03125f);     // /32 exact
        float dens = glibc_expf(-mean);
        float noise = jax_uniform_noise((unsigned)row);
        g_density[row] = __fadd_rn(dens, __fmul_rn(noise, 1e-6f));
    }
}

// dist-to-nearest-higher-density (exact min, order-free), score = dist * density
__global__ void distmin_kernel() {
    int row = blockIdx.x;
    int b = row >> 12;
    const float* dr   = g_dist + (size_t)row * NN;
    const float* dens = g_density + b * NN;
    float di   = g_density[row];
    float dmax = __uint_as_float(g_maxbits[b]);
    float mv = dmax;
    for (int j = threadIdx.x; j < NN; j += 256) {
        if (dens[j] > di) mv = fminf(mv, dr[j]);
    }
    unsigned mb = __reduce_min_sync(0xffffffffu, __float_as_uint(mv));
    __shared__ unsigned sm[8];
    if ((threadIdx.x & 31) == 0) sm[threadIdx.x >> 5] = mb;
    __syncthreads();
    if (threadIdx.x == 0) {
        unsigned mm = sm[0];
#pragma unroll
        for (int w = 1; w < 8; w++) mm = min(mm, sm[w]);
        g_score[row] = __fmul_rn(__uint_as_float(mm), di);
    }
}

// bitonic sort, key = (~score_bits << 32) | idx  -> top-K with lax.top_k ties
__global__ void topk_kernel(float* __restrict__ out_indexdown) {
    __shared__ unsigned long long keys[NN];   // 32 KB
    int b = blockIdx.x;
    int tid = threadIdx.x;                    // 512 threads
    for (int j = tid; j < NN; j += 512) {
        unsigned sb = __float_as_uint(g_score[b * NN + j]);
        keys[j] = ((unsigned long long)(~sb) << 32) | (unsigned)j;
    }
    __syncthreads();
    for (unsigned k = 2; k <= NN; k <<= 1) {
        for (unsigned st = k >> 1; st > 0; st >>= 1) {
            for (unsigned i = tid; i < NN; i += 512) {
                unsigned ixj = i ^ st;
                if (ixj > i) {
                    unsigned long long a = keys[i], c = keys[ixj];
                    bool up = ((i & k) == 0);
                    bool swap = up ? (a > c) : (a < c);
                    if (swap) { keys[i] = c; keys[ixj] = a; }
                }
            }
            __syncthreads();
        }
    }
    int idx = (int)(keys[tid] & 0xFFFFFFFFull);
    g_index_down[b * KK + tid] = idx;
    out_indexdown[b * KK + tid] = (float)idx;
}

// idx_cluster[b,j] = argmin_kk dist[b, center_kk, j]  (first-min, strict <)
__global__ void assign_kernel(float* __restrict__ out_idxcluster) {
    int b = blockIdx.y;
    int j = blockIdx.x * 256 + threadIdx.x;
    __shared__ int cen[KK];
    for (int t = threadIdx.x; t < KK; t += 256) cen[t] = g_index_down[b * KK + t];
    __syncthreads();
    const float* db = g_dist + (size_t)b * NN * NN;
    float best = 3.4e38f; int bi = 0;
    for (int kk = 0; kk < KK; kk++) {
        float v = db[(size_t)cen[kk] * NN + j];
        if (v < best) { best = v; bi = kk; }
    }
    out_idxcluster[b * NN + j] = (float)bi;
}

__global__ void scatter_kernel(float* __restrict__ out_idxcluster) {
    int t = blockIdx.x * 256 + threadIdx.x;
    if (t >= BB * KK) return;
    int b = t >> 9, kk = t & (KK - 1);
    out_idxcluster[b * NN + g_index_down[t]] = (float)kk;
}

__global__ void xdown_kernel(const float* __restrict__ x, float* __restrict__ out_xdown) {
    int t = blockIdx.x * 256 + threadIdx.x;
    if (t >= BB * KK * CC) return;
    int c = t & (CC - 1);
    int rest = t >> 8;
    int kk = rest & (KK - 1);
    int b = rest >> 9;
    out_xdown[t] = x[((size_t)b * NN + g_index_down[b * KK + kk]) * CC + c];
}

// ---------------- launch ----------------
extern "C" void kernel_launch(void* const* d_in, const int* in_sizes, int n_in,
                              void* d_out, int out_size) {
    const float* x = (const float*)d_in[0];
    float* out = (float*)d_out;
    float* out_indexdown  = out;                       // B*K
    float* out_idxcluster = out + BB * KK;             // B*N
    float* out_xdown      = out + BB * KK + BB * NN;   // B*K*C

    x2_kernel<<<(BB * NN + 255) / 256, 256>>>(x);

    dim3 gg(NPAIRS, 1, BB);
    dist_kernel<<<gg, 256>>>(x);

    knn_density_kernel<<<BB * NN, 256>>>();

    distmin_kernel<<<BB * NN, 256>>>();

    topk_kernel<<<BB, 512>>>(out_indexdown);

    assign_kernel<<<dim3(NN / 256, BB), 256>>>(out_idxcluster);
    scatter_kernel<<<(BB * KK + 255) / 256, 256>>>(out_idxcluster);
    xdown_kernel<<<(BB * KK * CC + 255) / 256, 256>>>(x, out_xdown);
}

// round 8
// speedup vs baseline: 2.0985x; 1.5726x over previous
#include <cuda_runtime.h>
#include <cmath>
#include <cstdint>

#define BB 4
#define NN 4096
#define CC 256
#define KK 512
#define KNNK 32

// ---------------- scratch (no allocations allowed) ----------------
__device__ float    g_dist[(size_t)BB * NN * NN];   // 268 MB pairwise distances
__device__ float    g_x2[BB * NN];
__device__ float    g_density[BB * NN];
__device__ float    g_score[BB * NN];
__device__ unsigned g_maxbits[BB];
__device__ int      g_index_down[BB * KK];

// ---------------- threefry2x32 (bit-exact JAX PRNG, key = (0,1)) ----------------
__device__ __forceinline__ unsigned rotl32(unsigned x, int r) {
    return (x << r) | (x >> (32 - r));
}

__device__ void threefry2x32(unsigned k1, unsigned k2, unsigned x0, unsigned x1,
                             unsigned& o0, unsigned& o1) {
    unsigned ks0 = k1, ks1 = k2, ks2 = k1 ^ k2 ^ 0x1BD11BDAu;
    const int ra[4] = {13, 15, 26, 6};
    const int rb[4] = {17, 29, 16, 24};
    x0 += ks0; x1 += ks1;
#pragma unroll
    for (int i = 0; i < 4; i++) { x0 += x1; x1 = rotl32(x1, ra[i]); x1 ^= x0; }
    x0 += ks1; x1 += ks2 + 1u;
#pragma unroll
    for (int i = 0; i < 4; i++) { x0 += x1; x1 = rotl32(x1, rb[i]); x1 ^= x0; }
    x0 += ks2; x1 += ks0 + 2u;
#pragma unroll
    for (int i = 0; i < 4; i++) { x0 += x1; x1 = rotl32(x1, ra[i]); x1 ^= x0; }
    x0 += ks0; x1 += ks1 + 3u;
#pragma unroll
    for (int i = 0; i < 4; i++) { x0 += x1; x1 = rotl32(x1, rb[i]); x1 ^= x0; }
    x0 += ks1; x1 += ks2 + 4u;
#pragma unroll
    for (int i = 0; i < 4; i++) { x0 += x1; x1 = rotl32(x1, ra[i]); x1 ^= x0; }
    x0 += ks2; x1 += ks0 + 5u;
    o0 = x0; o1 = x1;
}

// JAX threefry_partitionable random_bits (32-bit): counter = uint64 iota ->
// threefry2x32(key, 0, i), bits = o0 ^ o1. uniform = bitcast((bits>>9)|1.0f)-1.
__device__ float jax_uniform_noise(unsigned gid) {
    unsigned o0, o1;
    threefry2x32(0u, 1u, 0u, gid, o0, o1);
    unsigned bits = o0 ^ o1;
    unsigned fb = (bits >> 9) | 0x3f800000u;
    return __uint_as_float(fb) - 1.0f;
}

// ---------------- glibc expf (bit-exact port of sysdeps/ieee754/flt-32/e_expf.c) ----
__device__ __constant__ unsigned long long c_exp_tab[32] = {
    0x3ff0000000000000ULL, 0x3fefd9b0d3158574ULL, 0x3fefb5586cf9890fULL, 0x3fef9301d0125b51ULL,
    0x3fef72b83c7d517bULL, 0x3fef54873168b9aaULL, 0x3fef387a6e756238ULL, 0x3fef1e9df51fdee1ULL,
    0x3fef06fe0a31b715ULL, 0x3feef1a7373aa9cbULL, 0x3feedea64c123422ULL, 0x3feece086061892dULL,
    0x3feebfdad5362a27ULL, 0x3feeb42b569d4f82ULL, 0x3feeab07dd485429ULL, 0x3feea47eb03a5585ULL,
    0x3feea09e667f3bcdULL, 0x3fee9f75e8ec5f74ULL, 0x3feea11473eb0187ULL, 0x3feea589994cce13ULL,
    0x3feeace5422aa0dbULL, 0x3feeb737b0cdc5e5ULL, 0x3feec49182a3f090ULL, 0x3feed503b23e255dULL,
    0x3feee89f995ad3adULL, 0x3feeff76f2fb5e47ULL, 0x3fef199bdd85529cULL, 0x3fef3720dcef9069ULL,
    0x3fef5818dcfba487ULL, 0x3fef7c97337b9b5fULL, 0x3fefa4afa2a490daULL, 0x3fefd0765b6e4540ULL
};

__device__ float glibc_expf(float x) {
    const double InvLn2N = 0x1.71547652b82fep+5;          // N/ln2, N=32
    const double C0 = 0x1.c6af84b912394p-5 / (32.0 * 32.0 * 32.0);
    const double C1 = 0x1.ebfce50fac4f3p-3 / (32.0 * 32.0);
    const double C2 = 0x1.62e42ff0c52d6p-1 / 32.0;
    double xd = (double)x;
    double z  = InvLn2N * xd;
    double kd = rint(z);
    long long kis = __double2ll_rn(z);
    unsigned long long ki = (unsigned long long)kis;
    double r = z - kd;
    unsigned long long t = c_exp_tab[ki & 31] + (ki << 47);
    double s = __longlong_as_double((long long)t);
    double zz = fma(C0, r, C1);
    double r2 = r * r;
    double y  = fma(C2, r, 1.0);
    y = fma(zz, r2, y);
    return (float)(y * s);
}

// ---------------- f32x2 packed helpers ----------------
__device__ __forceinline__ unsigned long long pack_dup_f32(float a) {
    unsigned long long r;
    unsigned ai = __float_as_uint(a);
    asm("mov.b64 %0, {%1, %1};" : "=l"(r) : "r"(ai));
    return r;
}
__device__ __forceinline__ void fma2(unsigned long long& acc, unsigned long long a,
                                     unsigned long long b) {
    asm("fma.rn.f32x2 %0, %1, %2, %0;" : "+l"(acc) : "l"(a), "l"(b));
}
__device__ __forceinline__ void unpack2(unsigned long long v, float& lo, float& hi) {
    unsigned l, h;
    asm("mov.b64 {%0, %1}, %2;" : "=r"(l), "=r"(h) : "l"(v));
    lo = __uint_as_float(l); hi = __uint_as_float(h);
}

// ---------------- kernels ----------------

// x2 = sum(x*x, -1): 4 lane accumulators over k mod 4, unfused mul+add,
// horizontal combine (a0+a2)+(a1+a3). Also resets g_maxbits.
__global__ void x2_kernel(const float* __restrict__ x) {
    int row = blockIdx.x * blockDim.x + threadIdx.x;
    if (blockIdx.x == 0 && threadIdx.x < BB) g_maxbits[threadIdx.x] = 0u;
    if (row >= BB * NN) return;
    const float4* xp = (const float4*)(x + (size_t)row * CC);
    float a0 = 0.f, a1 = 0.f, a2 = 0.f, a3 = 0.f;
#pragma unroll 8
    for (int kb = 0; kb < CC / 4; kb++) {
        float4 v = xp[kb];
        a0 = __fadd_rn(a0, __fmul_rn(v.x, v.x));
        a1 = __fadd_rn(a1, __fmul_rn(v.y, v.y));
        a2 = __fadd_rn(a2, __fmul_rn(v.z, v.z));
        a3 = __fadd_rn(a3, __fmul_rn(v.w, v.w));
    }
    g_x2[row] = __fadd_rn(__fadd_rn(a0, a2), __fadd_rn(a1, a3));
}

// Triangular GEMM with packed fma.rn.f32x2 (2x fp32 rate, per-lane IEEE fp32
// FMA -> bit-identical per-element ascending-k chains). Symmetric mirror
// writes; per-batch max accumulated via warp reduce + atomicMax.
#define NTILE 32            // NN/128
#define NPAIRS 528          // NTILE*(NTILE+1)/2
__device__ __forceinline__ int tri_base(int i) { return i * (2 * NTILE + 1 - i) / 2; }

__global__ __launch_bounds__(256, 2) void dist_kernel(const float* __restrict__ x) {
    const int TS = 128, KC = 8;
    int b = blockIdx.z;
    int l = blockIdx.x;
    int ti = (int)((2 * NTILE + 1 - sqrtf((float)((2 * NTILE + 1) * (2 * NTILE + 1) - 8 * l))) * 0.5f);
    if (ti > 0 && tri_base(ti) > l) ti--;
    while (tri_base(ti + 1) <= l) ti++;
    int tj = ti + (l - tri_base(ti));
    int it = ti * TS;
    int jt = tj * TS;
    const float* xb = x + (size_t)b * NN * CC;

    __shared__ __align__(16) float As[KC][TS];
    __shared__ __align__(16) float Bs[KC][TS];

    int tid = threadIdx.x;         // 256 threads
    int tx = tid & 15, ty = tid >> 4;

    unsigned long long acc2[8][4];  // [u][vpair], lanes = (v=2vp, v=2vp+1)
#pragma unroll
    for (int u = 0; u < 8; u++)
#pragma unroll
        for (int vp = 0; vp < 4; vp++) acc2[u][vp] = 0ULL;

    for (int k0 = 0; k0 < CC; k0 += KC) {
        int e   = tid * 4;
        int row = e >> 3;      // /KC
        int kk  = e & 7;       // %KC  (0 or 4)
        float4 av = *(const float4*)(&xb[(size_t)(it + row) * CC + k0 + kk]);
        float4 bv = *(const float4*)(&xb[(size_t)(jt + row) * CC + k0 + kk]);
        As[kk + 0][row] = av.x; As[kk + 1][row] = av.y;
        As[kk + 2][row] = av.z; As[kk + 3][row] = av.w;
        Bs[kk + 0][row] = bv.x; Bs[kk + 1][row] = bv.y;
        Bs[kk + 2][row] = bv.z; Bs[kk + 3][row] = bv.w;
        __syncthreads();

#pragma unroll
        for (int kc = 0; kc < KC; kc++) {
            float4 a0 = *(const float4*)(&As[kc][ty * 8]);
            float4 a1 = *(const float4*)(&As[kc][ty * 8 + 4]);
            // B pairs straight from smem as packed 64-bit lanes
            double2 bd0 = *(const double2*)(&Bs[kc][tx * 8]);
            double2 bd1 = *(const double2*)(&Bs[kc][tx * 8 + 4]);
            unsigned long long b2[4];
            b2[0] = __double_as_longlong(bd0.x);
            b2[1] = __double_as_longlong(bd0.y);
            b2[2] = __double_as_longlong(bd1.x);
            b2[3] = __double_as_longlong(bd1.y);
            float a[8] = {a0.x, a0.y, a0.z, a0.w, a1.x, a1.y, a1.z, a1.w};
#pragma unroll
            for (int u = 0; u < 8; u++) {
                unsigned long long a2 = pack_dup_f32(a[u]);
#pragma unroll
                for (int vp = 0; vp < 4; vp++)
                    fma2(acc2[u][vp], a2, b2[vp]);
            }
        }
        __syncthreads();
    }

    // unpack + epilogue: d = sqrt(max(x2i + x2j - 2*dot, 0)) / 16
    float acc[8][8];
#pragma unroll
    for (int u = 0; u < 8; u++)
#pragma unroll
        for (int vp = 0; vp < 4; vp++)
            unpack2(acc2[u][vp], acc[u][2 * vp], acc[u][2 * vp + 1]);

    float x2i[8], x2j[8];
#pragma unroll
    for (int u = 0; u < 8; u++) x2i[u] = g_x2[b * NN + it + ty * 8 + u];
#pragma unroll
    for (int v = 0; v < 8; v++) x2j[v] = g_x2[b * NN + jt + tx * 8 + v];
    unsigned mbits = 0u;
#pragma unroll
    for (int u = 0; u < 8; u++) {
#pragma unroll
        for (int v = 0; v < 8; v++) {
            float s  = __fadd_rn(x2i[u], x2j[v]);
            float d2 = __fadd_rn(s, -__fmul_rn(2.0f, acc[u][v]));
            d2 = fmaxf(d2, 0.0f);
            float d = __fmul_rn(__fsqrt_rn(d2), 0.0625f);
            acc[u][v] = d;
            mbits = max(mbits, __float_as_uint(d));
        }
    }
    mbits = __reduce_max_sync(0xffffffffu, mbits);
    if ((tid & 31) == 0) atomicMax(&g_maxbits[b], mbits);

#pragma unroll
    for (int u = 0; u < 8; u++) {
        float* drow = g_dist + ((size_t)b * NN + it + ty * 8 + u) * NN + jt + tx * 8;
        *(float4*)(drow)     = make_float4(acc[u][0], acc[u][1], acc[u][2], acc[u][3]);
        *(float4*)(drow + 4) = make_float4(acc[u][4], acc[u][5], acc[u][6], acc[u][7]);
    }
    if (it != jt) {
#pragma unroll
        for (int v = 0; v < 8; v++) {
            float* drow = g_dist + ((size_t)b * NN + jt + tx * 8 + v) * NN + it + ty * 8;
            *(float4*)(drow)     = make_float4(acc[0][v], acc[1][v], acc[2][v], acc[3][v]);
            *(float4*)(drow + 4) = make_float4(acc[4][v], acc[5][v], acc[6][v], acc[7][v]);
        }
    }
}

// per-row 32 smallest: register-resident values (16/thread), cached thread-min,
// redux.min + 8-way combine per iteration, ballot-claimed removal. 2 barriers/iter.
__global__ void knn_density_kernel() {
    int row = blockIdx.x;                 // b*NN + i
    const float4* dr4 = (const float4*)(g_dist + (size_t)row * NN);
    int tid  = threadIdx.x;               // 256
    int lane = tid & 31, wid = tid >> 5;
    const unsigned REMOVED = 0xFFFFFFFFu;

    unsigned v[16];
#pragma unroll
    for (int i = 0; i < 4; i++) {
        float4 f = dr4[tid + 256 * i];
        v[i * 4 + 0] = __float_as_uint(f.x);
        v[i * 4 + 1] = __float_as_uint(f.y);
        v[i * 4 + 2] = __float_as_uint(f.z);
        v[i * 4 + 3] = __float_as_uint(f.w);
    }
    unsigned tmin = REMOVED;
#pragma unroll
    for (int i = 0; i < 16; i++) tmin = min(tmin, v[i]);

    __shared__ unsigned warpmin[8];
    __shared__ float sel[KNNK];

    for (int it = 0; it < KNNK; it++) {
        unsigned wmin = __reduce_min_sync(0xffffffffu, tmin);
        if (lane == 0) warpmin[wid] = wmin;
        __syncthreads();
        unsigned gmin = warpmin[0];
        int ownerwarp = 0;
#pragma unroll
        for (int w = 7; w >= 1; w--)
            if (warpmin[w] <= gmin) { }   // placeholder (computed below)
        // lowest warp achieving the min:
        gmin = warpmin[0]; ownerwarp = 0;
#pragma unroll
        for (int w = 1; w < 8; w++)
            if (warpmin[w] < gmin) { gmin = warpmin[w]; ownerwarp = w; }
        if (wid == ownerwarp) {
            unsigned ball = __ballot_sync(0xffffffffu, tmin == gmin);
            int ownerlane = __ffs(ball) - 1;
            if (lane == ownerlane) {
                bool removed = false;
                unsigned nm = REMOVED;
#pragma unroll
                for (int i = 0; i < 16; i++) {
                    if (!removed && v[i] == gmin) { v[i] = REMOVED; removed = true; }
                    nm = min(nm, v[i]);
                }
                tmin = nm;
                sel[it] = __uint_as_float(gmin);
            }
        }
        __syncthreads();
    }

    if (tid == 0) {
        float a[4] = {0.f, 0.f, 0.f, 0.f};
#pragma unroll
        for (int i = 0; i < KNNK; i += 4) {
#pragma unroll
            for (int l = 0; l < 4; l++)
                a[l] = __fadd_rn(a[l], __fmul_rn(sel[i + l], sel[i + l]));
        }
        float sum  = __fadd_rn(__fadd_rn(a[0], a[2]), __fadd_rn(a[1], a[3]));
        float mean = __fmul_rn(sum, 0.03125f);
        float dens = glibc_expf(-mean);
        float noise = jax_uniform_noise((unsigned)row);
        g_density[row] = __fadd_rn(dens, __fmul_rn(noise, 1e-6f));
    }
}

// dist-to-nearest-higher-density (vectorized, order-free min), score = dist*density
__global__ void distmin_kernel() {
    int row = blockIdx.x;
    int b = row >> 12;
    const float4* dr4   = (const float4*)(g_dist + (size_t)row * NN);
    const float4* dens4 = (const float4*)(g_density + b * NN);
    float di   = g_density[row];
    float mv = __uint_as_float(g_maxbits[b]);
    int tid = threadIdx.x;
#pragma unroll
    for (int i = 0; i < 4; i++) {
        float4 d = dr4[tid + 256 * i];
        float4 e = dens4[tid + 256 * i];
        if (e.x > di) mv = fminf(mv, d.x);
        if (e.y > di) mv = fminf(mv, d.y);
        if (e.z > di) mv = fminf(mv, d.z);
        if (e.w > di) mv = fminf(mv, d.w);
    }
    unsigned mb = __reduce_min_sync(0xffffffffu, __float_as_uint(mv));
    __shared__ unsigned sm[8];
    if ((tid & 31) == 0) sm[tid >> 5] = mb;
    __syncthreads();
    if (tid == 0) {
        unsigned mm = sm[0];
#pragma unroll
        for (int w = 1; w < 8; w++) mm = min(mm, sm[w]);
        g_score[row] = __fmul_rn(__uint_as_float(mm), di);
    }
}

// bitonic sort, key = (~score_bits << 32) | idx  -> top-K with lax.top_k ties
__global__ void topk_kernel(float* __restrict__ out_indexdown) {
    __shared__ unsigned long long keys[NN];   // 32 KB
    int b = blockIdx.x;
    int tid = threadIdx.x;                    // 512 threads
    for (int j = tid; j < NN; j += 512) {
        unsigned sb = __float_as_uint(g_score[b * NN + j]);
        keys[j] = ((unsigned long long)(~sb) << 32) | (unsigned)j;
    }
    __syncthreads();
    for (unsigned k = 2; k <= NN; k <<= 1) {
        for (unsigned st = k >> 1; st > 0; st >>= 1) {
            for (unsigned i = tid; i < NN; i += 512) {
                unsigned ixj = i ^ st;
                if (ixj > i) {
                    unsigned long long a = keys[i], c = keys[ixj];
                    bool up = ((i & k) == 0);
                    bool swap = up ? (a > c) : (a < c);
                    if (swap) { keys[i] = c; keys[ixj] = a; }
                }
            }
            __syncthreads();
        }
    }
    int idx = (int)(keys[tid] & 0xFFFFFFFFull);
    g_index_down[b * KK + tid] = idx;
    out_indexdown[b * KK + tid] = (float)idx;
}

// idx_cluster[b,j] = argmin_kk dist[b, center_kk, j]  (first-min, strict <)
__global__ void assign_kernel(float* __restrict__ out_idxcluster) {
    int b = blockIdx.y;
    int j = blockIdx.x * 256 + threadIdx.x;
    __shared__ int cen[KK];
    for (int t = threadIdx.x; t < KK; t += 256) cen[t] = g_index_down[b * KK + t];
    __syncthreads();
    const float* db = g_dist + (size_t)b * NN * NN;
    float best = 3.4e38f; int bi = 0;
    for (int kk = 0; kk < KK; kk++) {
        float v = db[(size_t)cen[kk] * NN + j];
        if (v < best) { best = v; bi = kk; }
    }
    out_idxcluster[b * NN + j] = (float)bi;
}

__global__ void scatter_kernel(float* __restrict__ out_idxcluster) {
    int t = blockIdx.x * 256 + threadIdx.x;
    if (t >= BB * KK) return;
    int b = t >> 9, kk = t & (KK - 1);
    out_idxcluster[b * NN + g_index_down[t]] = (float)kk;
}

__global__ void xdown_kernel(const float* __restrict__ x, float* __restrict__ out_xdown) {
    int t = blockIdx.x * 256 + threadIdx.x;
    if (t >= BB * KK * CC) return;
    int c = t & (CC - 1);
    int rest = t >> 8;
    int kk = rest & (KK - 1);
    int b = rest >> 9;
    out_xdown[t] = x[((size_t)b * NN + g_index_down[b * KK + kk]) * CC + c];
}

// ---------------- launch ----------------
extern "C" void kernel_launch(void* const* d_in, const int* in_sizes, int n_in,
                              void* d_out, int out_size) {
    const float* x = (const float*)d_in[0];
    float* out = (float*)d_out;
    float* out_indexdown  = out;                       // B*K
    float* out_idxcluster = out + BB * KK;             // B*N
    float* out_xdown      = out + BB * KK + BB * NN;   // B*K*C

    x2_kernel<<<(BB * NN + 255) / 256, 256>>>(x);

    dim3 gg(NPAIRS, 1, BB);
    dist_kernel<<<gg, 256>>>(x);

    knn_density_kernel<<<BB * NN, 256>>>();

    distmin_kernel<<<BB * NN, 256>>>();

    topk_kernel<<<BB, 512>>>(out_indexdown);

    assign_kernel<<<dim3(NN / 256, BB), 256>>>(out_idxcluster);
    scatter_kernel<<<(BB * KK + 255) / 256, 256>>>(out_idxcluster);
    xdown_kernel<<<(BB * KK * CC + 255) / 256, 256>>>(x, out_xdown);
}

// round 9
// speedup vs baseline: 2.2070x; 1.0517x over previous
#include <cuda_runtime.h>
#include <cmath>
#include <cstdint>

#define BB 4
#define NN 4096
#define CC 256
#define KK 512
#define KNNK 32

// ---------------- scratch (no allocations allowed) ----------------
__device__ float    g_dist[(size_t)BB * NN * NN];   // 268 MB pairwise distances
__device__ float    g_x2[BB * NN];
__device__ float    g_density[BB * NN];
__device__ float    g_score[BB * NN];
__device__ unsigned g_maxbits[BB];
__device__ int      g_index_down[BB * KK];

// ---------------- threefry2x32 (bit-exact JAX PRNG, key = (0,1)) ----------------
__device__ __forceinline__ unsigned rotl32(unsigned x, int r) {
    return (x << r) | (x >> (32 - r));
}

__device__ void threefry2x32(unsigned k1, unsigned k2, unsigned x0, unsigned x1,
                             unsigned& o0, unsigned& o1) {
    unsigned ks0 = k1, ks1 = k2, ks2 = k1 ^ k2 ^ 0x1BD11BDAu;
    const int ra[4] = {13, 15, 26, 6};
    const int rb[4] = {17, 29, 16, 24};
    x0 += ks0; x1 += ks1;
#pragma unroll
    for (int i = 0; i < 4; i++) { x0 += x1; x1 = rotl32(x1, ra[i]); x1 ^= x0; }
    x0 += ks1; x1 += ks2 + 1u;
#pragma unroll
    for (int i = 0; i < 4; i++) { x0 += x1; x1 = rotl32(x1, rb[i]); x1 ^= x0; }
    x0 += ks2; x1 += ks0 + 2u;
#pragma unroll
    for (int i = 0; i < 4; i++) { x0 += x1; x1 = rotl32(x1, ra[i]); x1 ^= x0; }
    x0 += ks0; x1 += ks1 + 3u;
#pragma unroll
    for (int i = 0; i < 4; i++) { x0 += x1; x1 = rotl32(x1, rb[i]); x1 ^= x0; }
    x0 += ks1; x1 += ks2 + 4u;
#pragma unroll
    for (int i = 0; i < 4; i++) { x0 += x1; x1 = rotl32(x1, ra[i]); x1 ^= x0; }
    x0 += ks2; x1 += ks0 + 5u;
    o0 = x0; o1 = x1;
}

// JAX threefry_partitionable random_bits (32-bit): counter = uint64 iota ->
// threefry2x32(key, 0, i), bits = o0 ^ o1. uniform = bitcast((bits>>9)|1.0f)-1.
__device__ float jax_uniform_noise(unsigned gid) {
    unsigned o0, o1;
    threefry2x32(0u, 1u, 0u, gid, o0, o1);
    unsigned bits = o0 ^ o1;
    unsigned fb = (bits >> 9) | 0x3f800000u;
    return __uint_as_float(fb) - 1.0f;
}

// ---------------- glibc expf (bit-exact port of sysdeps/ieee754/flt-32/e_expf.c) ----
__device__ __constant__ unsigned long long c_exp_tab[32] = {
    0x3ff0000000000000ULL, 0x3fefd9b0d3158574ULL, 0x3fefb5586cf9890fULL, 0x3fef9301d0125b51ULL,
    0x3fef72b83c7d517bULL, 0x3fef54873168b9aaULL, 0x3fef387a6e756238ULL, 0x3fef1e9df51fdee1ULL,
    0x3fef06fe0a31b715ULL, 0x3feef1a7373aa9cbULL, 0x3feedea64c123422ULL, 0x3feece086061892dULL,
    0x3feebfdad5362a27ULL, 0x3feeb42b569d4f82ULL, 0x3feeab07dd485429ULL, 0x3feea47eb03a5585ULL,
    0x3feea09e667f3bcdULL, 0x3fee9f75e8ec5f74ULL, 0x3feea11473eb0187ULL, 0x3feea589994cce13ULL,
    0x3feeace5422aa0dbULL, 0x3feeb737b0cdc5e5ULL, 0x3feec49182a3f090ULL, 0x3feed503b23e255dULL,
    0x3feee89f995ad3adULL, 0x3feeff76f2fb5e47ULL, 0x3fef199bdd85529cULL, 0x3fef3720dcef9069ULL,
    0x3fef5818dcfba487ULL, 0x3fef7c97337b9b5fULL, 0x3fefa4afa2a490daULL, 0x3fefd0765b6e4540ULL
};

__device__ float glibc_expf(float x) {
    const double InvLn2N = 0x1.71547652b82fep+5;          // N/ln2, N=32
    const double C0 = 0x1.c6af84b912394p-5 / (32.0 * 32.0 * 32.0);
    const double C1 = 0x1.ebfce50fac4f3p-3 / (32.0 * 32.0);
    const double C2 = 0x1.62e42ff0c52d6p-1 / 32.0;
    double xd = (double)x;
    double z  = InvLn2N * xd;
    double kd = rint(z);
    long long kis = __double2ll_rn(z);
    unsigned long long ki = (unsigned long long)kis;
    double r = z - kd;
    unsigned long long t = c_exp_tab[ki & 31] + (ki << 47);
    double s = __longlong_as_double((long long)t);
    double zz = fma(C0, r, C1);
    double r2 = r * r;
    double y  = fma(C2, r, 1.0);
    y = fma(zz, r2, y);
    return (float)(y * s);
}

// ---------------- f32x2 packed helpers ----------------
__device__ __forceinline__ unsigned long long pack_dup_f32(float a) {
    unsigned long long r;
    unsigned ai = __float_as_uint(a);
    asm("mov.b64 %0, {%1, %1};" : "=l"(r) : "r"(ai));
    return r;
}
__device__ __forceinline__ void fma2(unsigned long long& acc, unsigned long long a,
                                     unsigned long long b) {
    asm("fma.rn.f32x2 %0, %1, %2, %0;" : "+l"(acc) : "l"(a), "l"(b));
}
__device__ __forceinline__ void unpack2(unsigned long long v, float& lo, float& hi) {
    unsigned l, h;
    asm("mov.b64 {%0, %1}, %2;" : "=r"(l), "=r"(h) : "l"(v));
    lo = __uint_as_float(l); hi = __uint_as_float(h);
}

// ---------------- kernels ----------------

// x2 = sum(x*x, -1): 4 lane accumulators over k mod 4, unfused mul+add,
// horizontal combine (a0+a2)+(a1+a3). Also resets g_maxbits.
__global__ void x2_kernel(const float* __restrict__ x) {
    int row = blockIdx.x * blockDim.x + threadIdx.x;
    if (blockIdx.x == 0 && threadIdx.x < BB) g_maxbits[threadIdx.x] = 0u;
    if (row >= BB * NN) return;
    const float4* xp = (const float4*)(x + (size_t)row * CC);
    float a0 = 0.f, a1 = 0.f, a2 = 0.f, a3 = 0.f;
#pragma unroll 8
    for (int kb = 0; kb < CC / 4; kb++) {
        float4 v = xp[kb];
        a0 = __fadd_rn(a0, __fmul_rn(v.x, v.x));
        a1 = __fadd_rn(a1, __fmul_rn(v.y, v.y));
        a2 = __fadd_rn(a2, __fmul_rn(v.z, v.z));
        a3 = __fadd_rn(a3, __fmul_rn(v.w, v.w));
    }
    g_x2[row] = __fadd_rn(__fadd_rn(a0, a2), __fadd_rn(a1, a3));
}

// Triangular GEMM with packed fma.rn.f32x2, double-buffered smem + register
// prefetch (1 barrier per K-chunk). Per-element accumulation chain is the same
// ascending-k fma sequence -> bit-identical results. Symmetric mirror writes;
// per-batch max via warp reduce + atomicMax.
#define NTILE 32            // NN/128
#define NPAIRS 528          // NTILE*(NTILE+1)/2
#define KCH 16              // K-chunk
#define NCHUNK (CC / KCH)   // 16
__device__ __forceinline__ int tri_base(int i) { return i * (2 * NTILE + 1 - i) / 2; }

#define STORE_CHUNK(buf)                                                      \
    do {                                                                      \
        As[buf][kk0 + 0][row0] = pa0.x; As[buf][kk0 + 1][row0] = pa0.y;       \
        As[buf][kk0 + 2][row0] = pa0.z; As[buf][kk0 + 3][row0] = pa0.w;       \
        As[buf][kk0 + 0][row0 + 64] = pa1.x; As[buf][kk0 + 1][row0 + 64] = pa1.y; \
        As[buf][kk0 + 2][row0 + 64] = pa1.z; As[buf][kk0 + 3][row0 + 64] = pa1.w; \
        Bs[buf][kk0 + 0][row0] = pb0.x; Bs[buf][kk0 + 1][row0] = pb0.y;       \
        Bs[buf][kk0 + 2][row0] = pb0.z; Bs[buf][kk0 + 3][row0] = pb0.w;       \
        Bs[buf][kk0 + 0][row0 + 64] = pb1.x; Bs[buf][kk0 + 1][row0 + 64] = pb1.y; \
        Bs[buf][kk0 + 2][row0 + 64] = pb1.z; Bs[buf][kk0 + 3][row0 + 64] = pb1.w; \
    } while (0)

__global__ __launch_bounds__(256, 2) void dist_kernel(const float* __restrict__ x) {
    const int TS = 128;
    int b = blockIdx.z;
    int l = blockIdx.x;
    int ti = (int)((2 * NTILE + 1 - sqrtf((float)((2 * NTILE + 1) * (2 * NTILE + 1) - 8 * l))) * 0.5f);
    if (ti > 0 && tri_base(ti) > l) ti--;
    while (tri_base(ti + 1) <= l) ti++;
    int tj = ti + (l - tri_base(ti));
    int it = ti * TS;
    int jt = tj * TS;
    const float* xb = x + (size_t)b * NN * CC;

    __shared__ __align__(16) float As[2][KCH][TS];
    __shared__ __align__(16) float Bs[2][KCH][TS];

    int tid = threadIdx.x;         // 256 threads
    int tx = tid & 15, ty = tid >> 4;

    // loader mapping: thread covers (row0, kk0..kk0+3) and (row0+64, same kk)
    int row0 = tid >> 2;
    int kk0  = (tid & 3) * 4;
    const float* aptr = &xb[(size_t)(it + row0) * CC + kk0];
    const float* bptr = &xb[(size_t)(jt + row0) * CC + kk0];

    unsigned long long acc2[8][4];  // [u][vpair]
#pragma unroll
    for (int u = 0; u < 8; u++)
#pragma unroll
        for (int vp = 0; vp < 4; vp++) acc2[u][vp] = 0ULL;

    // prologue: chunk 0 -> buffer 0
    float4 pa0 = *(const float4*)(aptr);
    float4 pa1 = *(const float4*)(aptr + 64 * CC);
    float4 pb0 = *(const float4*)(bptr);
    float4 pb1 = *(const float4*)(bptr + 64 * CC);
    STORE_CHUNK(0);
    __syncthreads();

    for (int chunk = 0; chunk < NCHUNK; chunk++) {
        int cur = chunk & 1;
        if (chunk + 1 < NCHUNK) {
            int k0n = (chunk + 1) * KCH;
            pa0 = *(const float4*)(aptr + k0n);
            pa1 = *(const float4*)(aptr + 64 * CC + k0n);
            pb0 = *(const float4*)(bptr + k0n);
            pb1 = *(const float4*)(bptr + 64 * CC + k0n);
        }
#pragma unroll
        for (int kc = 0; kc < KCH; kc++) {
            float4 a0 = *(const float4*)(&As[cur][kc][ty * 8]);
            float4 a1 = *(const float4*)(&As[cur][kc][ty * 8 + 4]);
            double2 bd0 = *(const double2*)(&Bs[cur][kc][tx * 8]);
            double2 bd1 = *(const double2*)(&Bs[cur][kc][tx * 8 + 4]);
            unsigned long long b2[4];
            b2[0] = __double_as_longlong(bd0.x);
            b2[1] = __double_as_longlong(bd0.y);
            b2[2] = __double_as_longlong(bd1.x);
            b2[3] = __double_as_longlong(bd1.y);
            float a[8] = {a0.x, a0.y, a0.z, a0.w, a1.x, a1.y, a1.z, a1.w};
#pragma unroll
            for (int u = 0; u < 8; u++) {
                unsigned long long a2 = pack_dup_f32(a[u]);
#pragma unroll
                for (int vp = 0; vp < 4; vp++)
                    fma2(acc2[u][vp], a2, b2[vp]);
            }
        }
        if (chunk + 1 < NCHUNK) {
            int nxt = cur ^ 1;
            STORE_CHUNK(nxt);
            __syncthreads();
        }
    }

    // unpack + epilogue: d = sqrt(max(x2i + x2j - 2*dot, 0)) / 16
    float acc[8][8];
#pragma unroll
    for (int u = 0; u < 8; u++)
#pragma unroll
        for (int vp = 0; vp < 4; vp++)
            unpack2(acc2[u][vp], acc[u][2 * vp], acc[u][2 * vp + 1]);

    float x2i[8], x2j[8];
#pragma unroll
    for (int u = 0; u < 8; u++) x2i[u] = g_x2[b * NN + it + ty * 8 + u];
#pragma unroll
    for (int v = 0; v < 8; v++) x2j[v] = g_x2[b * NN + jt + tx * 8 + v];
    unsigned mbits = 0u;
#pragma unroll
    for (int u = 0; u < 8; u++) {
#pragma unroll
        for (int v = 0; v < 8; v++) {
            float s  = __fadd_rn(x2i[u], x2j[v]);
            float d2 = __fadd_rn(s, -__fmul_rn(2.0f, acc[u][v]));
            d2 = fmaxf(d2, 0.0f);
            float d = __fmul_rn(__fsqrt_rn(d2), 0.0625f);
            acc[u][v] = d;
            mbits = max(mbits, __float_as_uint(d));
        }
    }
    mbits = __reduce_max_sync(0xffffffffu, mbits);
    if ((tid & 31) == 0) atomicMax(&g_maxbits[b], mbits);

#pragma unroll
    for (int u = 0; u < 8; u++) {
        float* drow = g_dist + ((size_t)b * NN + it + ty * 8 + u) * NN + jt + tx * 8;
        *(float4*)(drow)     = make_float4(acc[u][0], acc[u][1], acc[u][2], acc[u][3]);
        *(float4*)(drow + 4) = make_float4(acc[u][4], acc[u][5], acc[u][6], acc[u][7]);
    }
    if (it != jt) {
#pragma unroll
        for (int v = 0; v < 8; v++) {
            float* drow = g_dist + ((size_t)b * NN + jt + tx * 8 + v) * NN + it + ty * 8;
            *(float4*)(drow)     = make_float4(acc[0][v], acc[1][v], acc[2][v], acc[3][v]);
            *(float4*)(drow + 4) = make_float4(acc[4][v], acc[5][v], acc[6][v], acc[7][v]);
        }
    }
}

// per-row 32 smallest: register-resident values (16/thread), cached thread-min,
// redux.min + 8-way combine per iteration, ballot-claimed removal.
__global__ void knn_density_kernel() {
    int row = blockIdx.x;                 // b*NN + i
    const float4* dr4 = (const float4*)(g_dist + (size_t)row * NN);
    int tid  = threadIdx.x;               // 256
    int lane = tid & 31, wid = tid >> 5;
    const unsigned REMOVED = 0xFFFFFFFFu;

    unsigned v[16];
#pragma unroll
    for (int i = 0; i < 4; i++) {
        float4 f = dr4[tid + 256 * i];
        v[i * 4 + 0] = __float_as_uint(f.x);
        v[i * 4 + 1] = __float_as_uint(f.y);
        v[i * 4 + 2] = __float_as_uint(f.z);
        v[i * 4 + 3] = __float_as_uint(f.w);
    }
    unsigned tmin = REMOVED;
#pragma unroll
    for (int i = 0; i < 16; i++) tmin = min(tmin, v[i]);

    __shared__ unsigned warpmin[8];
    __shared__ float sel[KNNK];

    for (int it = 0; it < KNNK; it++) {
        unsigned wmin = __reduce_min_sync(0xffffffffu, tmin);
        if (lane == 0) warpmin[wid] = wmin;
        __syncthreads();
        unsigned gmin = warpmin[0];
        int ownerwarp = 0;
#pragma unroll
        for (int w = 1; w < 8; w++)
            if (warpmin[w] < gmin) { gmin = warpmin[w]; ownerwarp = w; }
        if (wid == ownerwarp) {
            unsigned ball = __ballot_sync(0xffffffffu, tmin == gmin);
            int ownerlane = __ffs(ball) - 1;
            if (lane == ownerlane) {
                bool removed = false;
                unsigned nm = REMOVED;
#pragma unroll
                for (int i = 0; i < 16; i++) {
                    if (!removed && v[i] == gmin) { v[i] = REMOVED; removed = true; }
                    nm = min(nm, v[i]);
                }
                tmin = nm;
                sel[it] = __uint_as_float(gmin);
            }
        }
        __syncthreads();
    }

    if (tid == 0) {
        float a[4] = {0.f, 0.f, 0.f, 0.f};
#pragma unroll
        for (int i = 0; i < KNNK; i += 4) {
#pragma unroll
            for (int l = 0; l < 4; l++)
                a[l] = __fadd_rn(a[l], __fmul_rn(sel[i + l], sel[i + l]));
        }
        float sum  = __fadd_rn(__fadd_rn(a[0], a[2]), __fadd_rn(a[1], a[3]));
        float mean = __fmul_rn(sum, 0.03125f);
        float dens = glibc_expf(-mean);
        float noise = jax_uniform_noise((unsigned)row);
        g_density[row] = __fadd_rn(dens, __fmul_rn(noise, 1e-6f));
    }
}

// dist-to-nearest-higher-density (vectorized, order-free min), score = dist*density
__global__ void distmin_kernel() {
    int row = blockIdx.x;
    int b = row >> 12;
    const float4* dr4   = (const float4*)(g_dist + (size_t)row * NN);
    const float4* dens4 = (const float4*)(g_density + b * NN);
    float di   = g_density[row];
    float mv = __uint_as_float(g_maxbits[b]);
    int tid = threadIdx.x;
#pragma unroll
    for (int i = 0; i < 4; i++) {
        float4 d = dr4[tid + 256 * i];
        float4 e = dens4[tid + 256 * i];
        if (e.x > di) mv = fminf(mv, d.x);
        if (e.y > di) mv = fminf(mv, d.y);
        if (e.z > di) mv = fminf(mv, d.z);
        if (e.w > di) mv = fminf(mv, d.w);
    }
    unsigned mb = __reduce_min_sync(0xffffffffu, __float_as_uint(mv));
    __shared__ unsigned sm[8];
    if ((tid & 31) == 0) sm[tid >> 5] = mb;
    __syncthreads();
    if (tid == 0) {
        unsigned mm = sm[0];
#pragma unroll
        for (int w = 1; w < 8; w++) mm = min(mm, sm[w]);
        g_score[row] = __fmul_rn(__uint_as_float(mm), di);
    }
}

// bitonic sort, key = (~score_bits << 32) | idx  -> top-K with lax.top_k ties
__global__ void topk_kernel(float* __restrict__ out_indexdown) {
    __shared__ unsigned long long keys[NN];   // 32 KB
    int b = blockIdx.x;
    int tid = threadIdx.x;                    // 512 threads
    for (int j = tid; j < NN; j += 512) {
        unsigned sb = __float_as_uint(g_score[b * NN + j]);
        keys[j] = ((unsigned long long)(~sb) << 32) | (unsigned)j;
    }
    __syncthreads();
    for (unsigned k = 2; k <= NN; k <<= 1) {
        for (unsigned st = k >> 1; st > 0; st >>= 1) {
            for (unsigned i = tid; i < NN; i += 512) {
                unsigned ixj = i ^ st;
                if (ixj > i) {
                    unsigned long long a = keys[i], c = keys[ixj];
                    bool up = ((i & k) == 0);
                    bool swap = up ? (a > c) : (a < c);
                    if (swap) { keys[i] = c; keys[ixj] = a; }
                }
            }
            __syncthreads();
        }
    }
    int idx = (int)(keys[tid] & 0xFFFFFFFFull);
    g_index_down[b * KK + tid] = idx;
    out_indexdown[b * KK + tid] = (float)idx;
}

// idx_cluster[b,j] = argmin_kk dist[b, center_kk, j]  (first-min, strict <)
__global__ void assign_kernel(float* __restrict__ out_idxcluster) {
    int b = blockIdx.y;
    int j = blockIdx.x * 256 + threadIdx.x;
    __shared__ int cen[KK];
    for (int t = threadIdx.x; t < KK; t += 256) cen[t] = g_index_down[b * KK + t];
    __syncthreads();
    const float* db = g_dist + (size_t)b * NN * NN;
    float best = 3.4e38f; int bi = 0;
    for (int kk = 0; kk < KK; kk++) {
        float v = db[(size_t)cen[kk] * NN + j];
        if (v < best) { best = v; bi = kk; }
    }
    out_idxcluster[b * NN + j] = (float)bi;
}

__global__ void scatter_kernel(float* __restrict__ out_idxcluster) {
    int t = blockIdx.x * 256 + threadIdx.x;
    if (t >= BB * KK) return;
    int b = t >> 9, kk = t & (KK - 1);
    out_idxcluster[b * NN + g_index_down[t]] = (float)kk;
}

__global__ void xdown_kernel(const float* __restrict__ x, float* __restrict__ out_xdown) {
    int t = blockIdx.x * 256 + threadIdx.x;
    if (t >= BB * KK * CC) return;
    int c = t & (CC - 1);
    int rest = t >> 8;
    int kk = rest & (KK - 1);
    int b = rest >> 9;
    out_xdown[t] = x[((size_t)b * NN + g_index_down[b * KK + kk]) * CC + c];
}

// ---------------- launch ----------------
extern "C" void kernel_launch(void* const* d_in, const int* in_sizes, int n_in,
                              void* d_out, int out_size) {
    const float* x = (const float*)d_in[0];
    float* out = (float*)d_out;
    float* out_indexdown  = out;                       // B*K
    float* out_idxcluster = out + BB * KK;             // B*N
    float* out_xdown      = out + BB * KK + BB * NN;   // B*K*C

    x2_kernel<<<(BB * NN + 255) / 256, 256>>>(x);

    dim3 gg(NPAIRS, 1, BB);
    dist_kernel<<<gg, 256>>>(x);

    knn_density_kernel<<<BB * NN, 256>>>();

    distmin_kernel<<<BB * NN, 256>>>();

    topk_kernel<<<BB, 512>>>(out_indexdown);

    assign_kernel<<<dim3(NN / 256, BB), 256>>>(out_idxcluster);
    scatter_kernel<<<(BB * KK + 255) / 256, 256>>>(out_idxcluster);
    xdown_kernel<<<(BB * KK * CC + 255) / 256, 256>>>(x, out_xdown);
}